// round 14
// baseline (speedup 1.0000x reference)
#include <cuda_runtime.h>
#include <cuda_fp16.h>
#include <cstdint>
#include <math.h>

// ---------------------------------------------------------------------------
// SoftEmbRescore (sm_100 base ISA — tcgen05 unavailable in this build):
// ONE fused kernel (plus a tiny counter-reset launch):
//   bids 0..63  : build G = emb@emb^T (tf32 mma.sync -> fp16 g_h, e_norm),
//                 signal g_done. All wave-1 residents -> no deadlock.
//   bx == 0     : convert this m-block's 128 rows of x -> fp16 x_h,
//                 signal x_flag[by]. Converter bid < peer bids -> no deadlock.
//   everyone    : bounded-spin g_done / x_flag, then the R13 GEMM:
//                 dots = x_h @ G_h (fp16 m16n8k16, at the f32-accum HMMA
//                 floor ~492us), smem-staged s^2 partials, cross-CTA s
//                 exchange, in-register divide, single finalized out write.
// ---------------------------------------------------------------------------

namespace {
constexpr int MDIM = 65536;
constexpr int NDIM = 1024;
constexpr int KDIM = 1024;

constexpr int BM = 128;
constexpr int BN = 256;
constexpr int BK = 64;
constexpr int LDSH = BK + 8;                     // 72 halves = 144 B rows
constexpr int NTHREADS = 256;
constexpr int NSTAGE = 3;
constexpr int NT = KDIM / BK;                    // 16
constexpr int STAGE_HALVES = (BM + BN) * LDSH;   // 27648 halves = 55296 B
constexpr int SMEM_MAIN = NSTAGE * STAGE_HALVES * 2;  // 165888 B
constexpr int NCTA_N = NDIM / BN;                // 4
constexpr int NBLK_M = MDIM / BM;                // 512
constexpr int XS = BN + 8;                       // x-tile smem stride (halves)

constexpr int GBM = 128, GBN = 128, GBK = 16;
constexpr int GLDS = GBK + 4;
constexpr int GNT = KDIM / GBK;
constexpr int GSTAGE = (GBM + GBN) * GLDS;       // 5120 floats = 20 KB
constexpr int SPIN_MAX = 1 << 22;                // bounded: bug -> wrong ans, not hang
}

__device__ __align__(16) __half g_h[(size_t)NDIM * NDIM];     // 2 MB
__device__ __align__(16) __half x_h[(size_t)MDIM * KDIM];     // 128 MB
__device__ __align__(16) float e_norm[NDIM];
__device__ __align__(16) float s2_part[NCTA_N][MDIM];         // 1 MB
__device__ int g_cnt[NBLK_M];
__device__ int x_flag[NBLK_M];
__device__ int g_done;

// ============================ helpers ======================================

__device__ __forceinline__ uint32_t smem_u32(const void* p) {
    uint32_t a;
    asm("{ .reg .u64 t; cvta.to.shared.u64 t, %1; cvt.u32.u64 %0, t; }" : "=r"(a) : "l"(p));
    return a;
}
__device__ __forceinline__ uint32_t f2tf32(float f) {
    uint32_t r;
    asm("cvt.rna.tf32.f32 %0, %1;" : "=r"(r) : "f"(f));
    return r;
}
__device__ __forceinline__ void mma_tf32(float* d, const uint32_t* a, const uint32_t* b) {
    asm volatile(
        "mma.sync.aligned.m16n8k8.row.col.f32.tf32.tf32.f32 "
        "{%0,%1,%2,%3}, {%4,%5,%6,%7}, {%8,%9}, {%0,%1,%2,%3};"
        : "+f"(d[0]), "+f"(d[1]), "+f"(d[2]), "+f"(d[3])
        : "r"(a[0]), "r"(a[1]), "r"(a[2]), "r"(a[3]), "r"(b[0]), "r"(b[1]));
}
__device__ __forceinline__ void mma_f16(float* d, const uint32_t* a, const uint32_t* b) {
    asm volatile(
        "mma.sync.aligned.m16n8k16.row.col.f32.f16.f16.f32 "
        "{%0,%1,%2,%3}, {%4,%5,%6,%7}, {%8,%9}, {%0,%1,%2,%3};"
        : "+f"(d[0]), "+f"(d[1]), "+f"(d[2]), "+f"(d[3])
        : "r"(a[0]), "r"(a[1]), "r"(a[2]), "r"(a[3]), "r"(b[0]), "r"(b[1]));
}

#define CP_ASYNC16(dst, src) \
    asm volatile("cp.async.cg.shared.global [%0], [%1], 16;" :: "r"(dst), "l"(src))
#define CP_COMMIT() asm volatile("cp.async.commit_group;")
#define CP_WAIT2()  asm volatile("cp.async.wait_group 2;")
#define CP_WAIT1()  asm volatile("cp.async.wait_group 1;")
#define CP_WAIT0()  asm volatile("cp.async.wait_group 0;")

// =================== kernel 0: reset signals (graph-safe) ==================

__global__ void reset_kernel() {
    int i = blockIdx.x * 256 + threadIdx.x;
    if (i < NBLK_M) { g_cnt[i] = 0; x_flag[i] = 0; }
    if (i == 0) g_done = 0;
}

// ======================= fused kernel ======================================

__global__ __launch_bounds__(NTHREADS, 1)
void fused_kernel(float* __restrict__ out, const float* __restrict__ x,
                  const float* __restrict__ emb)
{
    extern __shared__ __align__(16) __half smem_h[];
    const int tid = threadIdx.x;
    const int warp = tid >> 5, lane = tid & 31;
    const int by = blockIdx.y, bx = blockIdx.x;
    const int bid = bx + NCTA_N * by;             // launch (flat) order
    const int m0 = by * BM;
    const int n0 = bx * BN;
    const int grp = lane >> 2, tig = lane & 3;

    // ---------------- phase A: G-builder (bids 0..63, all wave-1) ----------
    if (bid < 64) {
        float* smem = reinterpret_cast<float*>(smem_h);    // 40 KB of dynamic
        const int gm0 = (bid >> 3) * GBM;
        const int gn0 = (bid & 7) * GBN;

        auto load_stage = [&](int s, int kt) {
            const float* Ag = emb + (size_t)gm0 * KDIM + kt * GBK;
            const float* Bg = emb + (size_t)gn0 * KDIM + kt * GBK;
            float* Asm = smem + s * GSTAGE;
            float* Bsm = Asm + GBM * GLDS;
            #pragma unroll
            for (int i = 0; i < 2; ++i) {
                int chunk = tid + i * 256;
                int r = chunk >> 2;
                int c = (chunk & 3) * 4;
                CP_ASYNC16(smem_u32(Asm + r * GLDS + c), Ag + (size_t)r * KDIM + c);
                CP_ASYNC16(smem_u32(Bsm + r * GLDS + c), Bg + (size_t)r * KDIM + c);
            }
            CP_COMMIT();
        };

        const int mb = (warp & 3) * 32, nb = (warp >> 2) * 64;

        float gd[2][8][4];
        #pragma unroll
        for (int mi = 0; mi < 2; ++mi)
            #pragma unroll
            for (int ni = 0; ni < 8; ++ni)
                #pragma unroll
                for (int r = 0; r < 4; ++r) gd[mi][ni][r] = 0.f;

        load_stage(0, 0);
        for (int t = 0; t < GNT; ++t) {
            if (t + 1 < GNT) { load_stage((t + 1) & 1, t + 1); CP_WAIT1(); }
            else             { CP_WAIT0(); }
            __syncthreads();
            const float* Asm = smem + (t & 1) * GSTAGE;
            const float* Bsm = Asm + GBM * GLDS;
            #pragma unroll
            for (int kk = 0; kk < GBK; kk += 8) {
                uint32_t a[2][4];
                #pragma unroll
                for (int mi = 0; mi < 2; ++mi) {
                    const float* p = Asm + (mb + mi * 16 + grp) * GLDS + kk + tig;
                    a[mi][0] = f2tf32(p[0]);
                    a[mi][1] = f2tf32(p[8 * GLDS]);
                    a[mi][2] = f2tf32(p[4]);
                    a[mi][3] = f2tf32(p[8 * GLDS + 4]);
                }
                uint32_t b[8][2];
                #pragma unroll
                for (int ni = 0; ni < 8; ++ni) {
                    const float* p = Bsm + (nb + ni * 8 + grp) * GLDS + kk + tig;
                    b[ni][0] = f2tf32(p[0]);
                    b[ni][1] = f2tf32(p[4]);
                }
                #pragma unroll
                for (int mi = 0; mi < 2; ++mi)
                    #pragma unroll
                    for (int ni = 0; ni < 8; ++ni)
                        mma_tf32(gd[mi][ni], a[mi], b[ni]);
            }
            __syncthreads();
        }
        #pragma unroll
        for (int mi = 0; mi < 2; ++mi) {
            #pragma unroll
            for (int ni = 0; ni < 8; ++ni) {
                int row = gm0 + mb + mi * 16 + grp;
                int col = gn0 + nb + ni * 8 + 2 * tig;
                *reinterpret_cast<__half2*>(g_h + (size_t)row * NDIM + col) =
                    __floats2half2_rn(gd[mi][ni][0], gd[mi][ni][1]);
                *reinterpret_cast<__half2*>(g_h + (size_t)(row + 8) * NDIM + col) =
                    __floats2half2_rn(gd[mi][ni][2], gd[mi][ni][3]);
            }
        }
        if (gm0 == gn0) {
            __syncthreads();
            if (tid < GBM) {
                int j = gm0 + tid;
                e_norm[j] = sqrtf(fmaxf(__half2float(g_h[(size_t)j * NDIM + j]), 0.f));
            }
        }
        __threadfence();                          // release g_h / e_norm
        __syncthreads();
        if (tid == 0) atomicAdd(&g_done, 1);
    }

    // ---------------- phase B: converter (bx==0): x rows -> fp16 -----------
    if (bx == 0) {
        // 128 rows x 1024 cols; 16384 uint4-out chunks, 64 per thread.
        #pragma unroll 4
        for (int i = 0; i < 64; ++i) {
            int chunk = tid + i * NTHREADS;
            int r = chunk >> 7;                   // 128 chunks per row
            int c = (chunk & 127) * 8;
            const float* src = x + (size_t)(m0 + r) * KDIM + c;
            float4 v0 = *reinterpret_cast<const float4*>(src);
            float4 v1 = *reinterpret_cast<const float4*>(src + 4);
            __half2 h[4];
            h[0] = __floats2half2_rn(v0.x, v0.y);
            h[1] = __floats2half2_rn(v0.z, v0.w);
            h[2] = __floats2half2_rn(v1.x, v1.y);
            h[3] = __floats2half2_rn(v1.z, v1.w);
            *reinterpret_cast<uint4*>(x_h + (size_t)(m0 + r) * KDIM + c) =
                *reinterpret_cast<uint4*>(h);
        }
        __threadfence();                          // release x_h rows
        __syncthreads();
        if (tid == 0) atomicExch(&x_flag[by], 1);
    }

    // ---------------- phase C: gates (bounded spins) -----------------------
    if (tid == 0) {
        volatile int* g = &g_done;
        for (int it = 0; it < SPIN_MAX; ++it) if (*g >= 64) break;
        volatile int* f = x_flag + by;
        for (int it = 0; it < SPIN_MAX; ++it) if (*f) break;
        __threadfence();                          // acquire g_h, e_norm, x_h
    }
    __syncthreads();

    // ---------------- phase D: the R13 GEMM --------------------------------
    auto fill = [&](int kt) {
        __half* S = smem_h + (kt % NSTAGE) * STAGE_HALVES;
        const __half* Ag = x_h + (size_t)m0 * KDIM + kt * BK;
        const __half* Bg = g_h + (size_t)n0 * KDIM + kt * BK;
        #pragma unroll
        for (int i = 0; i < 12; ++i) {
            int chunk = tid + i * NTHREADS;
            int r = chunk >> 3;
            int c = (chunk & 7) * 8;
            const __half* src = (r < BM) ? (Ag + (size_t)r * KDIM + c)
                                         : (Bg + (size_t)(r - BM) * KDIM + c);
            CP_ASYNC16(smem_u32(S + r * LDSH + c), src);
        }
        CP_COMMIT();
    };

    const int mb = (warp & 1) * 64;
    const int nb = (warp >> 1) * 64;
    const int wn = warp >> 1;

    float d[4][8][4];
    #pragma unroll
    for (int mi = 0; mi < 4; ++mi)
        #pragma unroll
        for (int ni = 0; ni < 8; ++ni)
            #pragma unroll
            for (int r = 0; r < 4; ++r) d[mi][ni][r] = 0.f;

    fill(0); fill(1);

    for (int t = 0; t < NT; ++t) {
        if (t + 2 < NT) fill(t + 2);
        else            CP_COMMIT();
        CP_WAIT2();
        __syncthreads();

        const __half* Asm = smem_h + (t % NSTAGE) * STAGE_HALVES;
        const __half* Bsm = Asm + BM * LDSH;

        #pragma unroll
        for (int kk = 0; kk < BK; kk += 16) {
            uint32_t a[4][4];
            #pragma unroll
            for (int mi = 0; mi < 4; ++mi) {
                const __half* p = Asm + (mb + mi * 16 + grp) * LDSH + kk + 2 * tig;
                a[mi][0] = *reinterpret_cast<const uint32_t*>(p);
                a[mi][1] = *reinterpret_cast<const uint32_t*>(p + 8 * LDSH);
                a[mi][2] = *reinterpret_cast<const uint32_t*>(p + 8);
                a[mi][3] = *reinterpret_cast<const uint32_t*>(p + 8 * LDSH + 8);
            }
            uint32_t b[8][2];
            #pragma unroll
            for (int ni = 0; ni < 8; ++ni) {
                const __half* q = Bsm + (nb + ni * 8 + grp) * LDSH + kk + 2 * tig;
                b[ni][0] = *reinterpret_cast<const uint32_t*>(q);
                b[ni][1] = *reinterpret_cast<const uint32_t*>(q + 8);
            }
            #pragma unroll
            for (int mi = 0; mi < 4; ++mi)
                #pragma unroll
                for (int ni = 0; ni < 8; ++ni)
                    mma_f16(d[mi][ni], a[mi], b[ni]);
        }
        __syncthreads();
    }

    // stage this CTA's x tile into smem coalesced
    #pragma unroll
    for (int i = 0; i < 16; ++i) {
        int chunk = tid + i * NTHREADS;
        int r = chunk >> 5;
        int c = (chunk & 31) * 8;
        *reinterpret_cast<uint4*>(smem_h + r * XS + c) =
            *reinterpret_cast<const uint4*>(x_h + (size_t)(m0 + r) * NDIM + n0 + c);
    }
    __syncthreads();

    // s^2 partial for this column tile
    float rs[4][2] = {};
    #pragma unroll
    for (int mi = 0; mi < 4; ++mi) {
        #pragma unroll
        for (int ni = 0; ni < 8; ++ni) {
            int rl = mb + mi * 16 + grp;
            int cl = nb + ni * 8 + 2 * tig;
            float2 xa = __half22float2(
                *reinterpret_cast<const __half2*>(smem_h + rl * XS + cl));
            float2 xb = __half22float2(
                *reinterpret_cast<const __half2*>(smem_h + (rl + 8) * XS + cl));
            rs[mi][0] += d[mi][ni][0] * xa.x + d[mi][ni][1] * xa.y;
            rs[mi][1] += d[mi][ni][2] * xb.x + d[mi][ni][3] * xb.y;
        }
    }
    #pragma unroll
    for (int mi = 0; mi < 4; ++mi)
        #pragma unroll
        for (int h = 0; h < 2; ++h) {
            rs[mi][h] += __shfl_xor_sync(0xffffffffu, rs[mi][h], 1);
            rs[mi][h] += __shfl_xor_sync(0xffffffffu, rs[mi][h], 2);
        }

    float* s2buf = reinterpret_cast<float*>(smem_h + BM * XS);     // 512 f
    float* s_sh  = s2buf + 4 * BM;                                  // 128 f
    float* e_sh  = s_sh + BM;                                       // 256 f
    if (tig == 0) {
        #pragma unroll
        for (int mi = 0; mi < 4; ++mi) {
            s2buf[wn * BM + mb + mi * 16 + grp]     = rs[mi][0];
            s2buf[wn * BM + mb + mi * 16 + 8 + grp] = rs[mi][1];
        }
    }
    e_sh[tid] = e_norm[n0 + tid];
    __syncthreads();
    if (tid < BM) {
        s2_part[bx][m0 + tid] =
            s2buf[tid] + s2buf[BM + tid] + s2buf[2 * BM + tid] + s2buf[3 * BM + tid];
    }

    // publish partial, wait for the other 3 column-CTAs (bounded)
    __threadfence();
    __syncthreads();
    if (tid == 0) {
        atomicAdd(&g_cnt[by], 1);
        volatile int* c = g_cnt + by;
        for (int it = 0; it < SPIN_MAX; ++it) if (*c >= NCTA_N) break;
        __threadfence();
    }
    __syncthreads();

    // s_i for the whole m-block
    if (tid < BM) {
        float v = s2_part[0][m0 + tid] + s2_part[1][m0 + tid]
                + s2_part[2][m0 + tid] + s2_part[3][m0 + tid];
        s_sh[tid] = sqrtf(fmaxf(v, 0.f));
    }
    __syncthreads();

    // divide in registers, single finalized write of out
    #pragma unroll
    for (int mi = 0; mi < 4; ++mi) {
        int rl = mb + mi * 16 + grp;
        float s0 = s_sh[rl], s1 = s_sh[rl + 8];
        #pragma unroll
        for (int ni = 0; ni < 8; ++ni) {
            int cl = nb + ni * 8 + 2 * tig;
            float e0 = e_sh[cl], e1 = e_sh[cl + 1];
            int row = m0 + rl;
            int col = n0 + cl;
            float2 o0 = make_float2(
                __fdividef(d[mi][ni][0], fmaxf(s0 * e0, 1e-8f)),
                __fdividef(d[mi][ni][1], fmaxf(s0 * e1, 1e-8f)));
            float2 o1 = make_float2(
                __fdividef(d[mi][ni][2], fmaxf(s1 * e0, 1e-8f)),
                __fdividef(d[mi][ni][3], fmaxf(s1 * e1, 1e-8f)));
            *reinterpret_cast<float2*>(out + (size_t)row * NDIM + col)       = o0;
            *reinterpret_cast<float2*>(out + (size_t)(row + 8) * NDIM + col) = o1;
        }
    }
}

// ============================== launch =====================================

extern "C" void kernel_launch(void* const* d_in, const int* in_sizes, int n_in,
                              void* d_out, int out_size) {
    const float* x   = (const float*)d_in[0];   // [1, 65536, 1024] fp32
    const float* emb = (const float*)d_in[1];   // [1024, 1024] fp32
    float* out = (float*)d_out;                 // [1, 65536, 1024] fp32
    (void)in_sizes; (void)n_in; (void)out_size;

    cudaFuncSetAttribute(fused_kernel,
                         cudaFuncAttributeMaxDynamicSharedMemorySize, SMEM_MAIN);

    // 1) reset inter-CTA signals (graph-replay safe)
    reset_kernel<<<2, 256>>>();
    // 2) fused: G-build + x-convert + GEMM + s-exchange + finalize
    fused_kernel<<<dim3(NCTA_N, NBLK_M), NTHREADS, SMEM_MAIN>>>(out, x, emb);
}

// round 15
// speedup vs baseline: 1.0742x; 1.0742x over previous
#include <cuda_runtime.h>
#include <cuda_fp16.h>
#include <cstdint>
#include <math.h>

// ---------------------------------------------------------------------------
// SoftEmbRescore (sm_100 base ISA — tcgen05 unavailable in this build):
//   prep:  G = emb @ emb^T (tf32 mma.sync -> fp16 g_h, e_norm), 64 CTAs,
//          + exchange-counter reset. ~25us.
//   gemm:  dots = fp16(x) @ G_h — A is read DIRECTLY from fp32 x via
//          cp.async into fp32 A-stages and converted to fp16 in the
//          fragment load (same cvt.rn as the old x_h pass -> identical
//          numerics, but the 73us standalone convert pass is GONE and its
//          DRAM traffic overlaps the compute-bound mainloop).
//          Epilogue: smem-staged s^2 partials (x read fp32, cvt on stage),
//          cross-CTA s exchange (R13 pattern), in-register divide, single
//          finalized out write.
// ---------------------------------------------------------------------------

namespace {
constexpr int MDIM = 65536;
constexpr int NDIM = 1024;
constexpr int KDIM = 1024;

constexpr int BM = 128;
constexpr int BN = 256;
constexpr int BK = 64;
constexpr int LDSA = BK + 4;                     // 68 floats (fp32 A rows)
constexpr int LDSH = BK + 8;                     // 72 halves (fp16 B rows)
constexpr int NTHREADS = 256;
constexpr int NSTAGE = 3;
constexpr int NT = KDIM / BK;                    // 16
constexpr int A_STAGE_BYTES = BM * LDSA * 4;     // 34816
constexpr int B_STAGE_BYTES = BN * LDSH * 2;     // 36864
constexpr int STAGE_BYTES = A_STAGE_BYTES + B_STAGE_BYTES;  // 71680
constexpr int SMEM_MAIN = NSTAGE * STAGE_BYTES;  // 215040 (< 227KB opt-in)
constexpr int NCTA_N = NDIM / BN;                // 4
constexpr int NBLK_M = MDIM / BM;                // 512
constexpr int XS = BN + 8;                       // x-tile smem stride (halves)

constexpr int GBM = 128, GBN = 128, GBK = 16;
constexpr int GLDS = GBK + 4;
constexpr int GNT = KDIM / GBK;
constexpr int GSTAGE = (GBM + GBN) * GLDS;
constexpr int SPIN_MAX = 1 << 22;                // bounded: bug -> wrong answer
}

__device__ __align__(16) __half g_h[(size_t)NDIM * NDIM];     // 2 MB
__device__ __align__(16) float e_norm[NDIM];
__device__ __align__(16) float s2_part[NCTA_N][MDIM];         // 1 MB
__device__ int g_cnt[NBLK_M];

// ============================ helpers ======================================

__device__ __forceinline__ uint32_t smem_u32(const void* p) {
    uint32_t a;
    asm("{ .reg .u64 t; cvta.to.shared.u64 t, %1; cvt.u32.u64 %0, t; }" : "=r"(a) : "l"(p));
    return a;
}
__device__ __forceinline__ uint32_t f2tf32(float f) {
    uint32_t r;
    asm("cvt.rna.tf32.f32 %0, %1;" : "=r"(r) : "f"(f));
    return r;
}
__device__ __forceinline__ uint32_t pack_h2(float lo, float hi) {
    __half2 h = __floats2half2_rn(lo, hi);
    return *reinterpret_cast<uint32_t*>(&h);
}
__device__ __forceinline__ void mma_tf32(float* d, const uint32_t* a, const uint32_t* b) {
    asm volatile(
        "mma.sync.aligned.m16n8k8.row.col.f32.tf32.tf32.f32 "
        "{%0,%1,%2,%3}, {%4,%5,%6,%7}, {%8,%9}, {%0,%1,%2,%3};"
        : "+f"(d[0]), "+f"(d[1]), "+f"(d[2]), "+f"(d[3])
        : "r"(a[0]), "r"(a[1]), "r"(a[2]), "r"(a[3]), "r"(b[0]), "r"(b[1]));
}
__device__ __forceinline__ void mma_f16(float* d, const uint32_t* a, const uint32_t* b) {
    asm volatile(
        "mma.sync.aligned.m16n8k16.row.col.f32.f16.f16.f32 "
        "{%0,%1,%2,%3}, {%4,%5,%6,%7}, {%8,%9}, {%0,%1,%2,%3};"
        : "+f"(d[0]), "+f"(d[1]), "+f"(d[2]), "+f"(d[3])
        : "r"(a[0]), "r"(a[1]), "r"(a[2]), "r"(a[3]), "r"(b[0]), "r"(b[1]));
}

#define CP_ASYNC16(dst, src) \
    asm volatile("cp.async.cg.shared.global [%0], [%1], 16;" :: "r"(dst), "l"(src))
#define CP_COMMIT() asm volatile("cp.async.commit_group;")
#define CP_WAIT2()  asm volatile("cp.async.wait_group 2;")
#define CP_WAIT1()  asm volatile("cp.async.wait_group 1;")
#define CP_WAIT0()  asm volatile("cp.async.wait_group 0;")

// ====== kernel 1: prep = G-builder (64 CTAs) + counter reset ===============

__global__ __launch_bounds__(256, 2)
void prep_kernel(const float* __restrict__ emb)
{
    __shared__ __align__(16) float smem[2 * GSTAGE];
    const int tid = threadIdx.x;

    if (blockIdx.x == 0) {                        // reset exchange counters
        g_cnt[tid] = 0;
        g_cnt[tid + 256] = 0;
    }

    const int m0 = ((int)blockIdx.x >> 3) * GBM;
    const int n0 = ((int)blockIdx.x & 7) * GBN;
    const float* A = emb;

    auto load_stage = [&](int s, int kt) {
        const float* Ag = A + (size_t)m0 * KDIM + kt * GBK;
        const float* Bg = A + (size_t)n0 * KDIM + kt * GBK;
        float* Asm = smem + s * GSTAGE;
        float* Bsm = Asm + GBM * GLDS;
        #pragma unroll
        for (int i = 0; i < 2; ++i) {
            int chunk = tid + i * 256;
            int r = chunk >> 2;
            int c = (chunk & 3) * 4;
            CP_ASYNC16(smem_u32(Asm + r * GLDS + c), Ag + (size_t)r * KDIM + c);
            CP_ASYNC16(smem_u32(Bsm + r * GLDS + c), Bg + (size_t)r * KDIM + c);
        }
        CP_COMMIT();
    };

    const int warp = tid >> 5, lane = tid & 31;
    const int mb = (warp & 3) * 32, nb = (warp >> 2) * 64;
    const int grp = lane >> 2, tig = lane & 3;

    float d[2][8][4];
    #pragma unroll
    for (int mi = 0; mi < 2; ++mi)
        #pragma unroll
        for (int ni = 0; ni < 8; ++ni)
            #pragma unroll
            for (int r = 0; r < 4; ++r) d[mi][ni][r] = 0.f;

    load_stage(0, 0);
    for (int t = 0; t < GNT; ++t) {
        if (t + 1 < GNT) { load_stage((t + 1) & 1, t + 1); CP_WAIT1(); }
        else             { CP_WAIT0(); }
        __syncthreads();
        const float* Asm = smem + (t & 1) * GSTAGE;
        const float* Bsm = Asm + GBM * GLDS;
        #pragma unroll
        for (int kk = 0; kk < GBK; kk += 8) {
            uint32_t a[2][4];
            #pragma unroll
            for (int mi = 0; mi < 2; ++mi) {
                const float* p = Asm + (mb + mi * 16 + grp) * GLDS + kk + tig;
                a[mi][0] = f2tf32(p[0]);
                a[mi][1] = f2tf32(p[8 * GLDS]);
                a[mi][2] = f2tf32(p[4]);
                a[mi][3] = f2tf32(p[8 * GLDS + 4]);
            }
            uint32_t b[8][2];
            #pragma unroll
            for (int ni = 0; ni < 8; ++ni) {
                const float* p = Bsm + (nb + ni * 8 + grp) * GLDS + kk + tig;
                b[ni][0] = f2tf32(p[0]);
                b[ni][1] = f2tf32(p[4]);
            }
            #pragma unroll
            for (int mi = 0; mi < 2; ++mi)
                #pragma unroll
                for (int ni = 0; ni < 8; ++ni)
                    mma_tf32(d[mi][ni], a[mi], b[ni]);
        }
        __syncthreads();
    }
    #pragma unroll
    for (int mi = 0; mi < 2; ++mi) {
        #pragma unroll
        for (int ni = 0; ni < 8; ++ni) {
            int row = m0 + mb + mi * 16 + grp;
            int col = n0 + nb + ni * 8 + 2 * tig;
            *reinterpret_cast<__half2*>(g_h + (size_t)row * NDIM + col) =
                __floats2half2_rn(d[mi][ni][0], d[mi][ni][1]);
            *reinterpret_cast<__half2*>(g_h + (size_t)(row + 8) * NDIM + col) =
                __floats2half2_rn(d[mi][ni][2], d[mi][ni][3]);
        }
    }
    if (m0 == n0) {
        __syncthreads();
        if (tid < GBM) {
            int j = m0 + tid;
            e_norm[j] = sqrtf(fmaxf(__half2float(g_h[(size_t)j * NDIM + j]), 0.f));
        }
    }
}

// == kernel 2: GEMM (fp32-A direct) + s exchange + in-register finalize =====

__global__ __launch_bounds__(NTHREADS, 1)
void main_gemm_kernel(float* __restrict__ out, const float* __restrict__ x)
{
    extern __shared__ __align__(16) char smem_raw[];
    __half* smem_h = reinterpret_cast<__half*>(smem_raw);
    const int tid = threadIdx.x;
    const int m0 = blockIdx.y * BM;
    const int n0 = blockIdx.x * BN;

    auto fill = [&](int kt) {
        char* S = smem_raw + (kt % NSTAGE) * STAGE_BYTES;
        float*  Asm = reinterpret_cast<float*>(S);
        __half* Bsm = reinterpret_cast<__half*>(S + A_STAGE_BYTES);
        const float*  Ag = x + (size_t)m0 * KDIM + kt * BK;
        const __half* Bg = g_h + (size_t)n0 * KDIM + kt * BK;
        #pragma unroll
        for (int i = 0; i < 16; ++i) {
            int chunk = tid + i * NTHREADS;       // 0..4095 (16B chunks)
            if (chunk < 2048) {                   // A: 128 rows x 16 chunks (fp32)
                int r = chunk >> 4;
                int c = (chunk & 15) * 4;
                CP_ASYNC16(smem_u32(Asm + r * LDSA + c), Ag + (size_t)r * KDIM + c);
            } else {                              // B: 256 rows x 8 chunks (fp16)
                int c2 = chunk - 2048;
                int r = c2 >> 3;
                int c = (c2 & 7) * 8;
                CP_ASYNC16(smem_u32(Bsm + r * LDSH + c), Bg + (size_t)r * KDIM + c);
            }
        }
        CP_COMMIT();
    };

    const int warp = tid >> 5, lane = tid & 31;
    const int mb = (warp & 1) * 64;
    const int nb = (warp >> 1) * 64;
    const int wn = warp >> 1;
    const int grp = lane >> 2, tig = lane & 3;

    float d[4][8][4];
    #pragma unroll
    for (int mi = 0; mi < 4; ++mi)
        #pragma unroll
        for (int ni = 0; ni < 8; ++ni)
            #pragma unroll
            for (int r = 0; r < 4; ++r) d[mi][ni][r] = 0.f;

    fill(0); fill(1);

    for (int t = 0; t < NT; ++t) {
        if (t + 2 < NT) fill(t + 2);
        else            CP_COMMIT();
        CP_WAIT2();
        __syncthreads();

        char* S = smem_raw + (t % NSTAGE) * STAGE_BYTES;
        const float*  Asm = reinterpret_cast<const float*>(S);
        const __half* Bsm = reinterpret_cast<const __half*>(S + A_STAGE_BYTES);

        #pragma unroll
        for (int kk = 0; kk < BK; kk += 16) {
            uint32_t a[4][4];
            #pragma unroll
            for (int mi = 0; mi < 4; ++mi) {
                const float* p = Asm + (mb + mi * 16 + grp) * LDSA + kk + 2 * tig;
                float2 v0 = *reinterpret_cast<const float2*>(p);
                float2 v1 = *reinterpret_cast<const float2*>(p + 8 * LDSA);
                float2 v2 = *reinterpret_cast<const float2*>(p + 8);
                float2 v3 = *reinterpret_cast<const float2*>(p + 8 * LDSA + 8);
                a[mi][0] = pack_h2(v0.x, v0.y);   // cvt.rn — identical to old x_h
                a[mi][1] = pack_h2(v1.x, v1.y);
                a[mi][2] = pack_h2(v2.x, v2.y);
                a[mi][3] = pack_h2(v3.x, v3.y);
            }
            uint32_t b[8][2];
            #pragma unroll
            for (int ni = 0; ni < 8; ++ni) {
                const __half* q = Bsm + (nb + ni * 8 + grp) * LDSH + kk + 2 * tig;
                b[ni][0] = *reinterpret_cast<const uint32_t*>(q);
                b[ni][1] = *reinterpret_cast<const uint32_t*>(q + 8);
            }
            #pragma unroll
            for (int mi = 0; mi < 4; ++mi)
                #pragma unroll
                for (int ni = 0; ni < 8; ++ni)
                    mma_f16(d[mi][ni], a[mi], b[ni]);
        }
        __syncthreads();
    }

    // ---- stage this CTA's x tile into smem (fp32 read, fp16 store) ----
    #pragma unroll
    for (int i = 0; i < 16; ++i) {
        int chunk = tid + i * NTHREADS;           // 4096 chunks of 8 elems
        int r = chunk >> 5;
        int c = (chunk & 31) * 8;
        const float* src = x + (size_t)(m0 + r) * KDIM + n0 + c;
        float4 v0 = *reinterpret_cast<const float4*>(src);
        float4 v1 = *reinterpret_cast<const float4*>(src + 4);
        __half2 h[4];
        h[0] = __floats2half2_rn(v0.x, v0.y);
        h[1] = __floats2half2_rn(v0.z, v0.w);
        h[2] = __floats2half2_rn(v1.x, v1.y);
        h[3] = __floats2half2_rn(v1.z, v1.w);
        *reinterpret_cast<uint4*>(smem_h + r * XS + c) = *reinterpret_cast<uint4*>(h);
    }
    __syncthreads();

    // ---- s^2 partial for this column tile ----
    float rs[4][2] = {};
    #pragma unroll
    for (int mi = 0; mi < 4; ++mi) {
        #pragma unroll
        for (int ni = 0; ni < 8; ++ni) {
            int rl = mb + mi * 16 + grp;
            int cl = nb + ni * 8 + 2 * tig;
            float2 xa = __half22float2(
                *reinterpret_cast<const __half2*>(smem_h + rl * XS + cl));
            float2 xb = __half22float2(
                *reinterpret_cast<const __half2*>(smem_h + (rl + 8) * XS + cl));
            rs[mi][0] += d[mi][ni][0] * xa.x + d[mi][ni][1] * xa.y;
            rs[mi][1] += d[mi][ni][2] * xb.x + d[mi][ni][3] * xb.y;
        }
    }
    #pragma unroll
    for (int mi = 0; mi < 4; ++mi)
        #pragma unroll
        for (int h = 0; h < 2; ++h) {
            rs[mi][h] += __shfl_xor_sync(0xffffffffu, rs[mi][h], 1);
            rs[mi][h] += __shfl_xor_sync(0xffffffffu, rs[mi][h], 2);
        }

    float* s2buf = reinterpret_cast<float*>(smem_h + BM * XS);     // 512 f
    float* s_sh  = s2buf + 4 * BM;                                  // 128 f
    float* e_sh  = s_sh + BM;                                       // 256 f
    if (tig == 0) {
        #pragma unroll
        for (int mi = 0; mi < 4; ++mi) {
            s2buf[wn * BM + mb + mi * 16 + grp]     = rs[mi][0];
            s2buf[wn * BM + mb + mi * 16 + 8 + grp] = rs[mi][1];
        }
    }
    e_sh[tid] = e_norm[n0 + tid];
    __syncthreads();
    if (tid < BM) {
        s2_part[blockIdx.x][m0 + tid] =
            s2buf[tid] + s2buf[BM + tid] + s2buf[2 * BM + tid] + s2buf[3 * BM + tid];
    }

    // ---- publish partial, wait for the other 3 column-CTAs (bounded) ----
    __threadfence();
    __syncthreads();
    if (tid == 0) {
        atomicAdd(&g_cnt[blockIdx.y], 1);
        volatile int* c = g_cnt + blockIdx.y;
        for (int it = 0; it < SPIN_MAX; ++it) if (*c >= NCTA_N) break;
        __threadfence();
    }
    __syncthreads();

    // ---- s_i for the whole m-block ----
    if (tid < BM) {
        float v = s2_part[0][m0 + tid] + s2_part[1][m0 + tid]
                + s2_part[2][m0 + tid] + s2_part[3][m0 + tid];
        s_sh[tid] = sqrtf(fmaxf(v, 0.f));
    }
    __syncthreads();

    // ---- divide in registers, single finalized write of out ----
    #pragma unroll
    for (int mi = 0; mi < 4; ++mi) {
        int rl = mb + mi * 16 + grp;
        float s0 = s_sh[rl], s1 = s_sh[rl + 8];
        #pragma unroll
        for (int ni = 0; ni < 8; ++ni) {
            int cl = nb + ni * 8 + 2 * tig;
            float e0 = e_sh[cl], e1 = e_sh[cl + 1];
            int row = m0 + rl;
            int col = n0 + cl;
            float2 o0 = make_float2(
                __fdividef(d[mi][ni][0], fmaxf(s0 * e0, 1e-8f)),
                __fdividef(d[mi][ni][1], fmaxf(s0 * e1, 1e-8f)));
            float2 o1 = make_float2(
                __fdividef(d[mi][ni][2], fmaxf(s1 * e0, 1e-8f)),
                __fdividef(d[mi][ni][3], fmaxf(s1 * e1, 1e-8f)));
            *reinterpret_cast<float2*>(out + (size_t)row * NDIM + col)       = o0;
            *reinterpret_cast<float2*>(out + (size_t)(row + 8) * NDIM + col) = o1;
        }
    }
}

// ============================== launch =====================================

extern "C" void kernel_launch(void* const* d_in, const int* in_sizes, int n_in,
                              void* d_out, int out_size) {
    const float* x   = (const float*)d_in[0];   // [1, 65536, 1024] fp32
    const float* emb = (const float*)d_in[1];   // [1024, 1024] fp32
    float* out = (float*)d_out;                 // [1, 65536, 1024] fp32
    (void)in_sizes; (void)n_in; (void)out_size;

    cudaFuncSetAttribute(main_gemm_kernel,
                         cudaFuncAttributeMaxDynamicSharedMemorySize, SMEM_MAIN);

    // 1) prep: G + e_norm (64 CTAs) + counter reset (graph-replay safe)
    prep_kernel<<<64, 256>>>(emb);
    // 2) GEMM reading fp32 x directly (no x_h pass) + s exchange + finalize
    main_gemm_kernel<<<dim3(NCTA_N, NBLK_M), NTHREADS, SMEM_MAIN>>>(out, x);
}

// round 16
// speedup vs baseline: 1.2049x; 1.1216x over previous
#include <cuda_runtime.h>
#include <cuda_fp16.h>
#include <cstdint>
#include <math.h>

// ---------------------------------------------------------------------------
// SoftEmbRescore (sm_100 base ISA — tcgen05 unavailable in this build):
//   prep:  G = emb @ emb^T (tf32 mma.sync -> fp16, blocks 0..63) overlapped
//          with x_h = fp16(x) (blocks 64..); e_norm from diagonal CTAs;
//          per-m-block counters reset (graph-replay safe).
//   gemm:  dots = x_h @ G_h (fp16 m16n8k16, 128x256 CTA / 64x64 warp —
//          at the f32-accum HMMA rate floor, ~492us). Epilogue: smem-staged
//          s^2 partials, cross-CTA exchange (store+fence+atomic, bounded
//          spin) among the 4 column-CTAs of each m-block, in-register
//          divide, single finalized out write.
// R16 = R13 (best, 645us; R14 full-fusion and R15 direct-fp32-A both
// regressed and are reverted) with pipeline depth 3 -> 4 stages.
// ---------------------------------------------------------------------------

namespace {
constexpr int MDIM = 65536;
constexpr int NDIM = 1024;
constexpr int KDIM = 1024;

constexpr int BM = 128;
constexpr int BN = 256;
constexpr int BK = 64;
constexpr int LDSH = BK + 8;                     // 72 halves = 144 B rows
constexpr int NTHREADS = 256;
constexpr int NSTAGE = 4;
constexpr int NT = KDIM / BK;                    // 16
constexpr int STAGE_HALVES = (BM + BN) * LDSH;   // 27648 halves = 55296 B
constexpr int SMEM_MAIN = NSTAGE * STAGE_HALVES * 2;  // 221184 B (<227KB)
constexpr int NCTA_N = NDIM / BN;                // 4
constexpr int NBLK_M = MDIM / BM;                // 512
constexpr int XS = BN + 8;                       // x-tile smem stride (halves)

constexpr int GBM = 128, GBN = 128, GBK = 16;
constexpr int GLDS = GBK + 4;
constexpr int GNT = KDIM / GBK;
constexpr int GSTAGE = (GBM + GBN) * GLDS;
constexpr int SPIN_MAX = 1 << 22;                // bounded: bug -> wrong ans, not hang
}

__device__ __align__(16) __half g_h[(size_t)NDIM * NDIM];     // 2 MB
__device__ __align__(16) __half x_h[(size_t)MDIM * KDIM];     // 128 MB
__device__ __align__(16) float e_norm[NDIM];
__device__ __align__(16) float s2_part[NCTA_N][MDIM];         // 1 MB
__device__ int g_cnt[NBLK_M];

// ============================ helpers ======================================

__device__ __forceinline__ uint32_t smem_u32(const void* p) {
    uint32_t a;
    asm("{ .reg .u64 t; cvta.to.shared.u64 t, %1; cvt.u32.u64 %0, t; }" : "=r"(a) : "l"(p));
    return a;
}
__device__ __forceinline__ uint32_t f2tf32(float f) {
    uint32_t r;
    asm("cvt.rna.tf32.f32 %0, %1;" : "=r"(r) : "f"(f));
    return r;
}
__device__ __forceinline__ void mma_tf32(float* d, const uint32_t* a, const uint32_t* b) {
    asm volatile(
        "mma.sync.aligned.m16n8k8.row.col.f32.tf32.tf32.f32 "
        "{%0,%1,%2,%3}, {%4,%5,%6,%7}, {%8,%9}, {%0,%1,%2,%3};"
        : "+f"(d[0]), "+f"(d[1]), "+f"(d[2]), "+f"(d[3])
        : "r"(a[0]), "r"(a[1]), "r"(a[2]), "r"(a[3]), "r"(b[0]), "r"(b[1]));
}
__device__ __forceinline__ void mma_f16(float* d, const uint32_t* a, const uint32_t* b) {
    asm volatile(
        "mma.sync.aligned.m16n8k16.row.col.f32.f16.f16.f32 "
        "{%0,%1,%2,%3}, {%4,%5,%6,%7}, {%8,%9}, {%0,%1,%2,%3};"
        : "+f"(d[0]), "+f"(d[1]), "+f"(d[2]), "+f"(d[3])
        : "r"(a[0]), "r"(a[1]), "r"(a[2]), "r"(a[3]), "r"(b[0]), "r"(b[1]));
}

#define CP_ASYNC16(dst, src) \
    asm volatile("cp.async.cg.shared.global [%0], [%1], 16;" :: "r"(dst), "l"(src))
#define CP_COMMIT() asm volatile("cp.async.commit_group;")
#define CP_WAIT3()  asm volatile("cp.async.wait_group 3;")
#define CP_WAIT1()  asm volatile("cp.async.wait_group 1;")
#define CP_WAIT0()  asm volatile("cp.async.wait_group 0;")

// ====== kernel 1: prep = {G-builder (blocks 0..63) | x->fp16 (rest)} =======

__global__ __launch_bounds__(256)
void prep_kernel(const float* __restrict__ emb, const float* __restrict__ x)
{
    __shared__ __align__(16) float smem[2 * GSTAGE];
    const int tid = threadIdx.x;

    if (blockIdx.x >= 64) {
        if (blockIdx.x == 64) {                  // reset exchange counters
            if (tid < NBLK_M) g_cnt[tid] = 0;
            if (tid + 256 < NBLK_M) g_cnt[tid + 256] = 0;
        }
        size_t i = ((size_t)(blockIdx.x - 64) * 256 + tid) * 8;
        float4 v0 = *reinterpret_cast<const float4*>(x + i);
        float4 v1 = *reinterpret_cast<const float4*>(x + i + 4);
        __half2 h[4];
        h[0] = __floats2half2_rn(v0.x, v0.y);
        h[1] = __floats2half2_rn(v0.z, v0.w);
        h[2] = __floats2half2_rn(v1.x, v1.y);
        h[3] = __floats2half2_rn(v1.z, v1.w);
        *reinterpret_cast<uint4*>(x_h + i) = *reinterpret_cast<uint4*>(h);
        return;
    }

    const int m0 = (blockIdx.x >> 3) * GBM;
    const int n0 = (blockIdx.x & 7) * GBN;
    const float* A = emb;

    auto load_stage = [&](int s, int kt) {
        const float* Ag = A + (size_t)m0 * KDIM + kt * GBK;
        const float* Bg = A + (size_t)n0 * KDIM + kt * GBK;
        float* Asm = smem + s * GSTAGE;
        float* Bsm = Asm + GBM * GLDS;
        #pragma unroll
        for (int i = 0; i < 2; ++i) {
            int chunk = tid + i * 256;
            int r = chunk >> 2;
            int c = (chunk & 3) * 4;
            CP_ASYNC16(smem_u32(Asm + r * GLDS + c), Ag + (size_t)r * KDIM + c);
            CP_ASYNC16(smem_u32(Bsm + r * GLDS + c), Bg + (size_t)r * KDIM + c);
        }
        CP_COMMIT();
    };

    const int warp = tid >> 5, lane = tid & 31;
    const int mb = (warp & 3) * 32, nb = (warp >> 2) * 64;
    const int grp = lane >> 2, tig = lane & 3;

    float d[2][8][4];
    #pragma unroll
    for (int mi = 0; mi < 2; ++mi)
        #pragma unroll
        for (int ni = 0; ni < 8; ++ni)
            #pragma unroll
            for (int r = 0; r < 4; ++r) d[mi][ni][r] = 0.f;

    load_stage(0, 0);
    for (int t = 0; t < GNT; ++t) {
        if (t + 1 < GNT) { load_stage((t + 1) & 1, t + 1); CP_WAIT1(); }
        else             { CP_WAIT0(); }
        __syncthreads();
        const float* Asm = smem + (t & 1) * GSTAGE;
        const float* Bsm = Asm + GBM * GLDS;
        #pragma unroll
        for (int kk = 0; kk < GBK; kk += 8) {
            uint32_t a[2][4];
            #pragma unroll
            for (int mi = 0; mi < 2; ++mi) {
                const float* p = Asm + (mb + mi * 16 + grp) * GLDS + kk + tig;
                a[mi][0] = f2tf32(p[0]);
                a[mi][1] = f2tf32(p[8 * GLDS]);
                a[mi][2] = f2tf32(p[4]);
                a[mi][3] = f2tf32(p[8 * GLDS + 4]);
            }
            uint32_t b[8][2];
            #pragma unroll
            for (int ni = 0; ni < 8; ++ni) {
                const float* p = Bsm + (nb + ni * 8 + grp) * GLDS + kk + tig;
                b[ni][0] = f2tf32(p[0]);
                b[ni][1] = f2tf32(p[4]);
            }
            #pragma unroll
            for (int mi = 0; mi < 2; ++mi)
                #pragma unroll
                for (int ni = 0; ni < 8; ++ni)
                    mma_tf32(d[mi][ni], a[mi], b[ni]);
        }
        __syncthreads();
    }
    #pragma unroll
    for (int mi = 0; mi < 2; ++mi) {
        #pragma unroll
        for (int ni = 0; ni < 8; ++ni) {
            int row = m0 + mb + mi * 16 + grp;
            int col = n0 + nb + ni * 8 + 2 * tig;
            *reinterpret_cast<__half2*>(g_h + (size_t)row * NDIM + col) =
                __floats2half2_rn(d[mi][ni][0], d[mi][ni][1]);
            *reinterpret_cast<__half2*>(g_h + (size_t)(row + 8) * NDIM + col) =
                __floats2half2_rn(d[mi][ni][2], d[mi][ni][3]);
        }
    }
    if (m0 == n0) {
        __syncthreads();
        if (tid < GBM) {
            int j = m0 + tid;
            e_norm[j] = sqrtf(fmaxf(__half2float(g_h[(size_t)j * NDIM + j]), 0.f));
        }
    }
}

// == kernel 2: dots GEMM + cross-CTA s exchange + in-register finalize ======

__global__ __launch_bounds__(NTHREADS, 1)
void main_gemm_kernel(float* __restrict__ out)
{
    extern __shared__ __align__(16) __half smem_h[];
    const int tid = threadIdx.x;
    const int m0 = blockIdx.y * BM;
    const int n0 = blockIdx.x * BN;

    auto fill = [&](int kt) {
        __half* S = smem_h + (kt & 3) * STAGE_HALVES;
        const __half* Ag = x_h + (size_t)m0 * KDIM + kt * BK;
        const __half* Bg = g_h + (size_t)n0 * KDIM + kt * BK;
        #pragma unroll
        for (int i = 0; i < 12; ++i) {
            int chunk = tid + i * NTHREADS;
            int r = chunk >> 3;
            int c = (chunk & 7) * 8;
            const __half* src = (r < BM) ? (Ag + (size_t)r * KDIM + c)
                                         : (Bg + (size_t)(r - BM) * KDIM + c);
            CP_ASYNC16(smem_u32(S + r * LDSH + c), src);
        }
        CP_COMMIT();
    };

    const int warp = tid >> 5, lane = tid & 31;
    const int mb = (warp & 1) * 64;
    const int nb = (warp >> 1) * 64;
    const int wn = warp >> 1;
    const int grp = lane >> 2, tig = lane & 3;

    float d[4][8][4];
    #pragma unroll
    for (int mi = 0; mi < 4; ++mi)
        #pragma unroll
        for (int ni = 0; ni < 8; ++ni)
            #pragma unroll
            for (int r = 0; r < 4; ++r) d[mi][ni][r] = 0.f;

    fill(0); fill(1); fill(2);

    for (int t = 0; t < NT; ++t) {
        if (t + 3 < NT) fill(t + 3);
        else            CP_COMMIT();              // fixed group accounting
        CP_WAIT3();                               // stage t complete
        __syncthreads();

        const __half* Asm = smem_h + (t & 3) * STAGE_HALVES;
        const __half* Bsm = Asm + BM * LDSH;

        #pragma unroll
        for (int kk = 0; kk < BK; kk += 16) {
            uint32_t a[4][4];
            #pragma unroll
            for (int mi = 0; mi < 4; ++mi) {
                const __half* p = Asm + (mb + mi * 16 + grp) * LDSH + kk + 2 * tig;
                a[mi][0] = *reinterpret_cast<const uint32_t*>(p);
                a[mi][1] = *reinterpret_cast<const uint32_t*>(p + 8 * LDSH);
                a[mi][2] = *reinterpret_cast<const uint32_t*>(p + 8);
                a[mi][3] = *reinterpret_cast<const uint32_t*>(p + 8 * LDSH + 8);
            }
            uint32_t b[8][2];
            #pragma unroll
            for (int ni = 0; ni < 8; ++ni) {
                const __half* q = Bsm + (nb + ni * 8 + grp) * LDSH + kk + 2 * tig;
                b[ni][0] = *reinterpret_cast<const uint32_t*>(q);
                b[ni][1] = *reinterpret_cast<const uint32_t*>(q + 8);
            }
            #pragma unroll
            for (int mi = 0; mi < 4; ++mi)
                #pragma unroll
                for (int ni = 0; ni < 8; ++ni)
                    mma_f16(d[mi][ni], a[mi], b[ni]);
        }
        __syncthreads();
    }

    // ---- stage this CTA's x tile into smem COALESCED ----
    #pragma unroll
    for (int i = 0; i < 16; ++i) {
        int chunk = tid + i * NTHREADS;           // 4096 chunks of 8 halves
        int r = chunk >> 5;
        int c = (chunk & 31) * 8;
        *reinterpret_cast<uint4*>(smem_h + r * XS + c) =
            *reinterpret_cast<const uint4*>(x_h + (size_t)(m0 + r) * NDIM + n0 + c);
    }
    __syncthreads();

    // ---- s^2 partial for this column tile ----
    float rs[4][2] = {};
    #pragma unroll
    for (int mi = 0; mi < 4; ++mi) {
        #pragma unroll
        for (int ni = 0; ni < 8; ++ni) {
            int rl = mb + mi * 16 + grp;
            int cl = nb + ni * 8 + 2 * tig;
            float2 xa = __half22float2(
                *reinterpret_cast<const __half2*>(smem_h + rl * XS + cl));
            float2 xb = __half22float2(
                *reinterpret_cast<const __half2*>(smem_h + (rl + 8) * XS + cl));
            rs[mi][0] += d[mi][ni][0] * xa.x + d[mi][ni][1] * xa.y;
            rs[mi][1] += d[mi][ni][2] * xb.x + d[mi][ni][3] * xb.y;
        }
    }
    #pragma unroll
    for (int mi = 0; mi < 4; ++mi)
        #pragma unroll
        for (int h = 0; h < 2; ++h) {
            rs[mi][h] += __shfl_xor_sync(0xffffffffu, rs[mi][h], 1);
            rs[mi][h] += __shfl_xor_sync(0xffffffffu, rs[mi][h], 2);
        }

    float* s2buf = reinterpret_cast<float*>(smem_h + BM * XS);     // 512 f
    float* s_sh  = s2buf + 4 * BM;                                  // 128 f
    float* e_sh  = s_sh + BM;                                       // 256 f
    if (tig == 0) {
        #pragma unroll
        for (int mi = 0; mi < 4; ++mi) {
            s2buf[wn * BM + mb + mi * 16 + grp]     = rs[mi][0];
            s2buf[wn * BM + mb + mi * 16 + 8 + grp] = rs[mi][1];
        }
    }
    e_sh[tid] = e_norm[n0 + tid];                 // stage e for my columns
    __syncthreads();
    if (tid < BM) {
        s2_part[blockIdx.x][m0 + tid] =
            s2buf[tid] + s2buf[BM + tid] + s2buf[2 * BM + tid] + s2buf[3 * BM + tid];
    }

    // ---- publish partial, wait for the other 3 column-CTAs (bounded) ----
    __threadfence();                               // release partial writes
    __syncthreads();
    if (tid == 0) {
        atomicAdd(&g_cnt[blockIdx.y], 1);
        volatile int* c = g_cnt + blockIdx.y;
        for (int it = 0; it < SPIN_MAX; ++it)
            if (*c >= NCTA_N) break;
        __threadfence();                           // acquire peers' partials
    }
    __syncthreads();

    // ---- s_i for the whole m-block ----
    if (tid < BM) {
        float v = s2_part[0][m0 + tid] + s2_part[1][m0 + tid]
                + s2_part[2][m0 + tid] + s2_part[3][m0 + tid];
        s_sh[tid] = sqrtf(fmaxf(v, 0.f));
    }
    __syncthreads();

    // ---- divide in registers, single finalized write of out ----
    #pragma unroll
    for (int mi = 0; mi < 4; ++mi) {
        int rl = mb + mi * 16 + grp;
        float s0 = s_sh[rl], s1 = s_sh[rl + 8];
        #pragma unroll
        for (int ni = 0; ni < 8; ++ni) {
            int cl = nb + ni * 8 + 2 * tig;
            float e0 = e_sh[cl], e1 = e_sh[cl + 1];
            int row = m0 + rl;
            int col = n0 + cl;
            float2 o0 = make_float2(
                __fdividef(d[mi][ni][0], fmaxf(s0 * e0, 1e-8f)),
                __fdividef(d[mi][ni][1], fmaxf(s0 * e1, 1e-8f)));
            float2 o1 = make_float2(
                __fdividef(d[mi][ni][2], fmaxf(s1 * e0, 1e-8f)),
                __fdividef(d[mi][ni][3], fmaxf(s1 * e1, 1e-8f)));
            *reinterpret_cast<float2*>(out + (size_t)row * NDIM + col)       = o0;
            *reinterpret_cast<float2*>(out + (size_t)(row + 8) * NDIM + col) = o1;
        }
    }
}

// ============================== launch =====================================

extern "C" void kernel_launch(void* const* d_in, const int* in_sizes, int n_in,
                              void* d_out, int out_size) {
    const float* x   = (const float*)d_in[0];   // [1, 65536, 1024] fp32
    const float* emb = (const float*)d_in[1];   // [1024, 1024] fp32
    float* out = (float*)d_out;                 // [1, 65536, 1024] fp32
    (void)in_sizes; (void)n_in; (void)out_size;

    cudaFuncSetAttribute(main_gemm_kernel,
                         cudaFuncAttributeMaxDynamicSharedMemorySize, SMEM_MAIN);

    // 1) prep: G + e_norm (blocks 0..63) overlapped with x->fp16; counters reset
    prep_kernel<<<64 + (int)((size_t)MDIM * KDIM / 2048), 256>>>(emb, x);
    // 2) dots GEMM + cross-CTA s exchange + in-register finalize, one out write
    main_gemm_kernel<<<dim3(NCTA_N, NBLK_M), NTHREADS, SMEM_MAIN>>>(out);
}

// round 17
// speedup vs baseline: 1.2085x; 1.0030x over previous
#include <cuda_runtime.h>
#include <cuda_fp16.h>
#include <cstdint>
#include <math.h>

// ---------------------------------------------------------------------------
// SoftEmbRescore (sm_100 base ISA — tcgen05 unavailable in this build):
//   prep:  G = emb @ emb^T (tf32 mma.sync -> fp16, blocks 0..63) overlapped
//          with x_h = fp16(x) (blocks 64..); e_norm from diagonal CTAs;
//          per-m-block counters reset (graph-replay safe).
//   gemm:  dots = x_h @ G_h (fp16 m16n8k16, 128x256 CTA / 64x64 warp —
//          at the f32-accum HMMA rate floor). Epilogue: smem-staged s^2
//          partials, cross-CTA exchange (bounded spin), in-register divide,
//          single finalized out write.
// R17 = R16 with SINGLE-SYNC mainloop: order per stage is
//   WAIT2 -> sync -> fill(t+3) -> MMA(t)
// The one sync both publishes stage t's fills and proves all warps finished
// MMA(t-1) before buffer (t-1)&3 is refilled. Commit accounting: prologue=3,
// commits at iter t = t+3, wait_group 2 => stages 0..t complete (tail keeps
// the invariant with an empty commit). Halves barrier count (32 -> 16).
// ---------------------------------------------------------------------------

namespace {
constexpr int MDIM = 65536;
constexpr int NDIM = 1024;
constexpr int KDIM = 1024;

constexpr int BM = 128;
constexpr int BN = 256;
constexpr int BK = 64;
constexpr int LDSH = BK + 8;                     // 72 halves = 144 B rows
constexpr int NTHREADS = 256;
constexpr int NSTAGE = 4;
constexpr int NT = KDIM / BK;                    // 16
constexpr int STAGE_HALVES = (BM + BN) * LDSH;   // 27648 halves = 55296 B
constexpr int SMEM_MAIN = NSTAGE * STAGE_HALVES * 2;  // 221184 B (<227KB)
constexpr int NCTA_N = NDIM / BN;                // 4
constexpr int NBLK_M = MDIM / BM;                // 512
constexpr int XS = BN + 8;                       // x-tile smem stride (halves)

constexpr int GBM = 128, GBN = 128, GBK = 16;
constexpr int GLDS = GBK + 4;
constexpr int GNT = KDIM / GBK;
constexpr int GSTAGE = (GBM + GBN) * GLDS;
constexpr int SPIN_MAX = 1 << 22;                // bounded: bug -> wrong ans, not hang
}

__device__ __align__(16) __half g_h[(size_t)NDIM * NDIM];     // 2 MB
__device__ __align__(16) __half x_h[(size_t)MDIM * KDIM];     // 128 MB
__device__ __align__(16) float e_norm[NDIM];
__device__ __align__(16) float s2_part[NCTA_N][MDIM];         // 1 MB
__device__ int g_cnt[NBLK_M];

// ============================ helpers ======================================

__device__ __forceinline__ uint32_t smem_u32(const void* p) {
    uint32_t a;
    asm("{ .reg .u64 t; cvta.to.shared.u64 t, %1; cvt.u32.u64 %0, t; }" : "=r"(a) : "l"(p));
    return a;
}
__device__ __forceinline__ uint32_t f2tf32(float f) {
    uint32_t r;
    asm("cvt.rna.tf32.f32 %0, %1;" : "=r"(r) : "f"(f));
    return r;
}
__device__ __forceinline__ void mma_tf32(float* d, const uint32_t* a, const uint32_t* b) {
    asm volatile(
        "mma.sync.aligned.m16n8k8.row.col.f32.tf32.tf32.f32 "
        "{%0,%1,%2,%3}, {%4,%5,%6,%7}, {%8,%9}, {%0,%1,%2,%3};"
        : "+f"(d[0]), "+f"(d[1]), "+f"(d[2]), "+f"(d[3])
        : "r"(a[0]), "r"(a[1]), "r"(a[2]), "r"(a[3]), "r"(b[0]), "r"(b[1]));
}
__device__ __forceinline__ void mma_f16(float* d, const uint32_t* a, const uint32_t* b) {
    asm volatile(
        "mma.sync.aligned.m16n8k16.row.col.f32.f16.f16.f32 "
        "{%0,%1,%2,%3}, {%4,%5,%6,%7}, {%8,%9}, {%0,%1,%2,%3};"
        : "+f"(d[0]), "+f"(d[1]), "+f"(d[2]), "+f"(d[3])
        : "r"(a[0]), "r"(a[1]), "r"(a[2]), "r"(a[3]), "r"(b[0]), "r"(b[1]));
}

#define CP_ASYNC16(dst, src) \
    asm volatile("cp.async.cg.shared.global [%0], [%1], 16;" :: "r"(dst), "l"(src))
#define CP_COMMIT() asm volatile("cp.async.commit_group;")
#define CP_WAIT2()  asm volatile("cp.async.wait_group 2;")
#define CP_WAIT1()  asm volatile("cp.async.wait_group 1;")
#define CP_WAIT0()  asm volatile("cp.async.wait_group 0;")

// ====== kernel 1: prep = {G-builder (blocks 0..63) | x->fp16 (rest)} =======

__global__ __launch_bounds__(256)
void prep_kernel(const float* __restrict__ emb, const float* __restrict__ x)
{
    __shared__ __align__(16) float smem[2 * GSTAGE];
    const int tid = threadIdx.x;

    if (blockIdx.x >= 64) {
        if (blockIdx.x == 64) {                  // reset exchange counters
            if (tid < NBLK_M) g_cnt[tid] = 0;
            if (tid + 256 < NBLK_M) g_cnt[tid + 256] = 0;
        }
        size_t i = ((size_t)(blockIdx.x - 64) * 256 + tid) * 8;
        float4 v0 = *reinterpret_cast<const float4*>(x + i);
        float4 v1 = *reinterpret_cast<const float4*>(x + i + 4);
        __half2 h[4];
        h[0] = __floats2half2_rn(v0.x, v0.y);
        h[1] = __floats2half2_rn(v0.z, v0.w);
        h[2] = __floats2half2_rn(v1.x, v1.y);
        h[3] = __floats2half2_rn(v1.z, v1.w);
        *reinterpret_cast<uint4*>(x_h + i) = *reinterpret_cast<uint4*>(h);
        return;
    }

    const int m0 = (blockIdx.x >> 3) * GBM;
    const int n0 = (blockIdx.x & 7) * GBN;
    const float* A = emb;

    auto load_stage = [&](int s, int kt) {
        const float* Ag = A + (size_t)m0 * KDIM + kt * GBK;
        const float* Bg = A + (size_t)n0 * KDIM + kt * GBK;
        float* Asm = smem + s * GSTAGE;
        float* Bsm = Asm + GBM * GLDS;
        #pragma unroll
        for (int i = 0; i < 2; ++i) {
            int chunk = tid + i * 256;
            int r = chunk >> 2;
            int c = (chunk & 3) * 4;
            CP_ASYNC16(smem_u32(Asm + r * GLDS + c), Ag + (size_t)r * KDIM + c);
            CP_ASYNC16(smem_u32(Bsm + r * GLDS + c), Bg + (size_t)r * KDIM + c);
        }
        CP_COMMIT();
    };

    const int warp = tid >> 5, lane = tid & 31;
    const int mb = (warp & 3) * 32, nb = (warp >> 2) * 64;
    const int grp = lane >> 2, tig = lane & 3;

    float d[2][8][4];
    #pragma unroll
    for (int mi = 0; mi < 2; ++mi)
        #pragma unroll
        for (int ni = 0; ni < 8; ++ni)
            #pragma unroll
            for (int r = 0; r < 4; ++r) d[mi][ni][r] = 0.f;

    load_stage(0, 0);
    for (int t = 0; t < GNT; ++t) {
        if (t + 1 < GNT) { load_stage((t + 1) & 1, t + 1); CP_WAIT1(); }
        else             { CP_WAIT0(); }
        __syncthreads();
        const float* Asm = smem + (t & 1) * GSTAGE;
        const float* Bsm = Asm + GBM * GLDS;
        #pragma unroll
        for (int kk = 0; kk < GBK; kk += 8) {
            uint32_t a[2][4];
            #pragma unroll
            for (int mi = 0; mi < 2; ++mi) {
                const float* p = Asm + (mb + mi * 16 + grp) * GLDS + kk + tig;
                a[mi][0] = f2tf32(p[0]);
                a[mi][1] = f2tf32(p[8 * GLDS]);
                a[mi][2] = f2tf32(p[4]);
                a[mi][3] = f2tf32(p[8 * GLDS + 4]);
            }
            uint32_t b[8][2];
            #pragma unroll
            for (int ni = 0; ni < 8; ++ni) {
                const float* p = Bsm + (nb + ni * 8 + grp) * GLDS + kk + tig;
                b[ni][0] = f2tf32(p[0]);
                b[ni][1] = f2tf32(p[4]);
            }
            #pragma unroll
            for (int mi = 0; mi < 2; ++mi)
                #pragma unroll
                for (int ni = 0; ni < 8; ++ni)
                    mma_tf32(d[mi][ni], a[mi], b[ni]);
        }
        __syncthreads();
    }
    #pragma unroll
    for (int mi = 0; mi < 2; ++mi) {
        #pragma unroll
        for (int ni = 0; ni < 8; ++ni) {
            int row = m0 + mb + mi * 16 + grp;
            int col = n0 + nb + ni * 8 + 2 * tig;
            *reinterpret_cast<__half2*>(g_h + (size_t)row * NDIM + col) =
                __floats2half2_rn(d[mi][ni][0], d[mi][ni][1]);
            *reinterpret_cast<__half2*>(g_h + (size_t)(row + 8) * NDIM + col) =
                __floats2half2_rn(d[mi][ni][2], d[mi][ni][3]);
        }
    }
    if (m0 == n0) {
        __syncthreads();
        if (tid < GBM) {
            int j = m0 + tid;
            e_norm[j] = sqrtf(fmaxf(__half2float(g_h[(size_t)j * NDIM + j]), 0.f));
        }
    }
}

// == kernel 2: dots GEMM (single-sync pipeline) + s exchange + finalize =====

__global__ __launch_bounds__(NTHREADS, 1)
void main_gemm_kernel(float* __restrict__ out)
{
    extern __shared__ __align__(16) __half smem_h[];
    const int tid = threadIdx.x;
    const int m0 = blockIdx.y * BM;
    const int n0 = blockIdx.x * BN;

    auto fill = [&](int kt) {
        __half* S = smem_h + (kt & 3) * STAGE_HALVES;
        const __half* Ag = x_h + (size_t)m0 * KDIM + kt * BK;
        const __half* Bg = g_h + (size_t)n0 * KDIM + kt * BK;
        #pragma unroll
        for (int i = 0; i < 12; ++i) {
            int chunk = tid + i * NTHREADS;
            int r = chunk >> 3;
            int c = (chunk & 7) * 8;
            const __half* src = (r < BM) ? (Ag + (size_t)r * KDIM + c)
                                         : (Bg + (size_t)(r - BM) * KDIM + c);
            CP_ASYNC16(smem_u32(S + r * LDSH + c), src);
        }
        CP_COMMIT();
    };

    const int warp = tid >> 5, lane = tid & 31;
    const int mb = (warp & 1) * 64;
    const int nb = (warp >> 1) * 64;
    const int wn = warp >> 1;
    const int grp = lane >> 2, tig = lane & 3;

    float d[4][8][4];
    #pragma unroll
    for (int mi = 0; mi < 4; ++mi)
        #pragma unroll
        for (int ni = 0; ni < 8; ++ni)
            #pragma unroll
            for (int r = 0; r < 4; ++r) d[mi][ni][r] = 0.f;

    fill(0); fill(1); fill(2);                    // 3 groups in flight

    for (int t = 0; t < NT; ++t) {
        // commits issued so far = t + 3  =>  wait_group 2 completes stage t
        CP_WAIT2();
        __syncthreads();       // stage t visible to all; MMAs(t-1) done by all
        if (t + 3 < NT) fill(t + 3);              // refills buf (t-1)&3: safe
        else            CP_COMMIT();              // keep commit count = t+4

        const __half* Asm = smem_h + (t & 3) * STAGE_HALVES;
        const __half* Bsm = Asm + BM * LDSH;

        #pragma unroll
        for (int kk = 0; kk < BK; kk += 16) {
            uint32_t a[4][4];
            #pragma unroll
            for (int mi = 0; mi < 4; ++mi) {
                const __half* p = Asm + (mb + mi * 16 + grp) * LDSH + kk + 2 * tig;
                a[mi][0] = *reinterpret_cast<const uint32_t*>(p);
                a[mi][1] = *reinterpret_cast<const uint32_t*>(p + 8 * LDSH);
                a[mi][2] = *reinterpret_cast<const uint32_t*>(p + 8);
                a[mi][3] = *reinterpret_cast<const uint32_t*>(p + 8 * LDSH + 8);
            }
            uint32_t b[8][2];
            #pragma unroll
            for (int ni = 0; ni < 8; ++ni) {
                const __half* q = Bsm + (nb + ni * 8 + grp) * LDSH + kk + 2 * tig;
                b[ni][0] = *reinterpret_cast<const uint32_t*>(q);
                b[ni][1] = *reinterpret_cast<const uint32_t*>(q + 8);
            }
            #pragma unroll
            for (int mi = 0; mi < 4; ++mi)
                #pragma unroll
                for (int ni = 0; ni < 8; ++ni)
                    mma_f16(d[mi][ni], a[mi], b[ni]);
        }
    }
    __syncthreads();                              // before epilogue smem reuse

    // ---- stage this CTA's x tile into smem COALESCED ----
    #pragma unroll
    for (int i = 0; i < 16; ++i) {
        int chunk = tid + i * NTHREADS;           // 4096 chunks of 8 halves
        int r = chunk >> 5;
        int c = (chunk & 31) * 8;
        *reinterpret_cast<uint4*>(smem_h + r * XS + c) =
            *reinterpret_cast<const uint4*>(x_h + (size_t)(m0 + r) * NDIM + n0 + c);
    }
    __syncthreads();

    // ---- s^2 partial for this column tile ----
    float rs[4][2] = {};
    #pragma unroll
    for (int mi = 0; mi < 4; ++mi) {
        #pragma unroll
        for (int ni = 0; ni < 8; ++ni) {
            int rl = mb + mi * 16 + grp;
            int cl = nb + ni * 8 + 2 * tig;
            float2 xa = __half22float2(
                *reinterpret_cast<const __half2*>(smem_h + rl * XS + cl));
            float2 xb = __half22float2(
                *reinterpret_cast<const __half2*>(smem_h + (rl + 8) * XS + cl));
            rs[mi][0] += d[mi][ni][0] * xa.x + d[mi][ni][1] * xa.y;
            rs[mi][1] += d[mi][ni][2] * xb.x + d[mi][ni][3] * xb.y;
        }
    }
    #pragma unroll
    for (int mi = 0; mi < 4; ++mi)
        #pragma unroll
        for (int h = 0; h < 2; ++h) {
            rs[mi][h] += __shfl_xor_sync(0xffffffffu, rs[mi][h], 1);
            rs[mi][h] += __shfl_xor_sync(0xffffffffu, rs[mi][h], 2);
        }

    float* s2buf = reinterpret_cast<float*>(smem_h + BM * XS);     // 512 f
    float* s_sh  = s2buf + 4 * BM;                                  // 128 f
    float* e_sh  = s_sh + BM;                                       // 256 f
    if (tig == 0) {
        #pragma unroll
        for (int mi = 0; mi < 4; ++mi) {
            s2buf[wn * BM + mb + mi * 16 + grp]     = rs[mi][0];
            s2buf[wn * BM + mb + mi * 16 + 8 + grp] = rs[mi][1];
        }
    }
    e_sh[tid] = e_norm[n0 + tid];                 // stage e for my columns
    __syncthreads();
    if (tid < BM) {
        s2_part[blockIdx.x][m0 + tid] =
            s2buf[tid] + s2buf[BM + tid] + s2buf[2 * BM + tid] + s2buf[3 * BM + tid];
    }

    // ---- publish partial, wait for the other 3 column-CTAs (bounded) ----
    __threadfence();                               // release partial writes
    __syncthreads();
    if (tid == 0) {
        atomicAdd(&g_cnt[blockIdx.y], 1);
        volatile int* c = g_cnt + blockIdx.y;
        for (int it = 0; it < SPIN_MAX; ++it)
            if (*c >= NCTA_N) break;
        __threadfence();                           // acquire peers' partials
    }
    __syncthreads();

    // ---- s_i for the whole m-block ----
    if (tid < BM) {
        float v = s2_part[0][m0 + tid] + s2_part[1][m0 + tid]
                + s2_part[2][m0 + tid] + s2_part[3][m0 + tid];
        s_sh[tid] = sqrtf(fmaxf(v, 0.f));
    }
    __syncthreads();

    // ---- divide in registers, single finalized write of out ----
    #pragma unroll
    for (int mi = 0; mi < 4; ++mi) {
        int rl = mb + mi * 16 + grp;
        float s0 = s_sh[rl], s1 = s_sh[rl + 8];
        #pragma unroll
        for (int ni = 0; ni < 8; ++ni) {
            int cl = nb + ni * 8 + 2 * tig;
            float e0 = e_sh[cl], e1 = e_sh[cl + 1];
            int row = m0 + rl;
            int col = n0 + cl;
            float2 o0 = make_float2(
                __fdividef(d[mi][ni][0], fmaxf(s0 * e0, 1e-8f)),
                __fdividef(d[mi][ni][1], fmaxf(s0 * e1, 1e-8f)));
            float2 o1 = make_float2(
                __fdividef(d[mi][ni][2], fmaxf(s1 * e0, 1e-8f)),
                __fdividef(d[mi][ni][3], fmaxf(s1 * e1, 1e-8f)));
            *reinterpret_cast<float2*>(out + (size_t)row * NDIM + col)       = o0;
            *reinterpret_cast<float2*>(out + (size_t)(row + 8) * NDIM + col) = o1;
        }
    }
}

// ============================== launch =====================================

extern "C" void kernel_launch(void* const* d_in, const int* in_sizes, int n_in,
                              void* d_out, int out_size) {
    const float* x   = (const float*)d_in[0];   // [1, 65536, 1024] fp32
    const float* emb = (const float*)d_in[1];   // [1024, 1024] fp32
    float* out = (float*)d_out;                 // [1, 65536, 1024] fp32
    (void)in_sizes; (void)n_in; (void)out_size;

    cudaFuncSetAttribute(main_gemm_kernel,
                         cudaFuncAttributeMaxDynamicSharedMemorySize, SMEM_MAIN);

    // 1) prep: G + e_norm (blocks 0..63) overlapped with x->fp16; counters reset
    prep_kernel<<<64 + (int)((size_t)MDIM * KDIM / 2048), 256>>>(emb, x);
    // 2) dots GEMM (single-sync pipeline) + s exchange + in-register finalize
    main_gemm_kernel<<<dim3(NCTA_N, NBLK_M), NTHREADS, SMEM_MAIN>>>(out);
}